// round 1
// baseline (speedup 1.0000x reference)
#include <cuda_runtime.h>
#include <cuda_bf16.h>
#include <math.h>

// Problem constants
#define EMBED_DIM 256
#define TOTAL_ATTN 128
#define MAXB 32768

typedef unsigned long long ull;

// ---------------- scratch (device globals; no allocation allowed) ----------------
__device__ float g_Q  [(size_t)MAXB * 128];   // q projections      [B,128]
__device__ float g_RK [(size_t)MAXB * 512];   // rk = Wk_h q_h      [B,2,256]
__device__ float g_PO [(size_t)MAXB * 512];   // attn-pooled nb     [B,2,256]
__device__ float g_CTX[(size_t)MAXB * 128];   // ctx (pre-Wo)       [B,128]

// ---------------- f32x2 helpers (packed FMA: 2x fp32 throughput) ----------------
__device__ __forceinline__ ull pk2(float x, float y) {
    ull r; asm("mov.b64 %0, {%1, %2};" : "=l"(r) : "f"(x), "f"(y)); return r;
}
__device__ __forceinline__ void fma2(ull &d, ull a, ull b) {
    asm("fma.rn.f32x2 %0, %1, %2, %0;" : "+l"(d) : "l"(a), "l"(b));
}
__device__ __forceinline__ float2 up2(ull v) {
    float2 r; asm("mov.b64 {%0, %1}, %2;" : "=f"(r.x), "=f"(r.y) : "l"(v)); return r;
}
__device__ __forceinline__ float wredsum(float v) {
    #pragma unroll
    for (int o = 16; o >= 1; o >>= 1) v += __shfl_xor_sync(0xffffffffu, v, o);
    return v;
}

// =================================================================================
// G1:  Q[B,128] = C[B,256] @ Wq[256,128]
// tile: 128 rows x 128 cols, k-chunks of 16. 256 threads, 8x8 register tile.
// =================================================================================
__global__ void __launch_bounds__(256) k_q(const float* __restrict__ A,
                                           const float* __restrict__ W) {
    __shared__ __align__(16) float As[16][132];  // [kk][row] transposed
    __shared__ __align__(16) float Bs[16][128];
    int tid = threadIdx.x;
    int tx = tid & 15, ty = tid >> 4;
    long row0 = (long)blockIdx.x * 128;
    ull acc[8][4];
    #pragma unroll
    for (int i = 0; i < 8; i++)
        #pragma unroll
        for (int j = 0; j < 4; j++) acc[i][j] = 0ULL;

    for (int k0 = 0; k0 < 256; k0 += 16) {
        #pragma unroll
        for (int it = 0; it < 2; it++) {
            int t = tid + it * 256;
            int r = t >> 2, f = t & 3;
            float4 v = *(const float4*)(A + (row0 + r) * 256 + k0 + f * 4);
            As[f*4+0][r] = v.x; As[f*4+1][r] = v.y; As[f*4+2][r] = v.z; As[f*4+3][r] = v.w;
            int kk = t >> 5, c = t & 31;
            *(float4*)&Bs[kk][c*4] = *(const float4*)(W + (k0 + kk) * 128 + c * 4);
        }
        __syncthreads();
        #pragma unroll
        for (int kk = 0; kk < 16; kk++) {
            float4 b0 = *(float4*)&Bs[kk][tx*8];
            float4 b1 = *(float4*)&Bs[kk][tx*8+4];
            ull bp0 = pk2(b0.x,b0.y), bp1 = pk2(b0.z,b0.w);
            ull bp2 = pk2(b1.x,b1.y), bp3 = pk2(b1.z,b1.w);
            #pragma unroll
            for (int i = 0; i < 8; i++) {
                float a = As[kk][ty*8+i];
                ull a2 = pk2(a, a);
                fma2(acc[i][0], a2, bp0); fma2(acc[i][1], a2, bp1);
                fma2(acc[i][2], a2, bp2); fma2(acc[i][3], a2, bp3);
            }
        }
        __syncthreads();
    }
    #pragma unroll
    for (int i = 0; i < 8; i++) {
        float2 f0 = up2(acc[i][0]), f1 = up2(acc[i][1]);
        float2 f2 = up2(acc[i][2]), f3 = up2(acc[i][3]);
        long r = row0 + ty*8 + i;
        *(float4*)(g_Q + r*128 + tx*8)   = make_float4(f0.x, f0.y, f1.x, f1.y);
        *(float4*)(g_Q + r*128 + tx*8+4) = make_float4(f2.x, f2.y, f3.x, f3.y);
    }
}

// =================================================================================
// G2:  RK[b, h*256+d] = sum_j Q[b, h*64+j] * Wk[d, h*64+j]     (K=64)
// grid.y in 0..3 selects (h, d-half). B-operand loaded transposed from Wk.
// =================================================================================
__global__ void __launch_bounds__(256) k_rk(const float* __restrict__ Wk) {
    __shared__ __align__(16) float As[16][132];
    __shared__ __align__(16) float Bs[16][132];
    int tid = threadIdx.x;
    int tx = tid & 15, ty = tid >> 4;
    long row0 = (long)blockIdx.x * 128;
    int by = blockIdx.y;
    int h = by >> 1, d0 = (by & 1) * 128;
    ull acc[8][4];
    #pragma unroll
    for (int i = 0; i < 8; i++)
        #pragma unroll
        for (int j = 0; j < 4; j++) acc[i][j] = 0ULL;

    for (int k0 = 0; k0 < 64; k0 += 16) {
        #pragma unroll
        for (int it = 0; it < 2; it++) {
            int t = tid + it * 256;
            int r = t >> 2, f = t & 3;
            float4 va = *(const float4*)(g_Q + (row0 + r) * 128 + h * 64 + k0 + f * 4);
            As[f*4+0][r] = va.x; As[f*4+1][r] = va.y; As[f*4+2][r] = va.z; As[f*4+3][r] = va.w;
            float4 vb = *(const float4*)(Wk + (long)(d0 + r) * 128 + h * 64 + k0 + f * 4);
            Bs[f*4+0][r] = vb.x; Bs[f*4+1][r] = vb.y; Bs[f*4+2][r] = vb.z; Bs[f*4+3][r] = vb.w;
        }
        __syncthreads();
        #pragma unroll
        for (int kk = 0; kk < 16; kk++) {
            float4 b0 = *(float4*)&Bs[kk][tx*8];
            float4 b1 = *(float4*)&Bs[kk][tx*8+4];
            ull bp0 = pk2(b0.x,b0.y), bp1 = pk2(b0.z,b0.w);
            ull bp2 = pk2(b1.x,b1.y), bp3 = pk2(b1.z,b1.w);
            #pragma unroll
            for (int i = 0; i < 8; i++) {
                float a = As[kk][ty*8+i];
                ull a2 = pk2(a, a);
                fma2(acc[i][0], a2, bp0); fma2(acc[i][1], a2, bp1);
                fma2(acc[i][2], a2, bp2); fma2(acc[i][3], a2, bp3);
            }
        }
        __syncthreads();
    }
    #pragma unroll
    for (int i = 0; i < 8; i++) {
        float2 f0 = up2(acc[i][0]), f1 = up2(acc[i][1]);
        float2 f2 = up2(acc[i][2]), f3 = up2(acc[i][3]);
        long r = row0 + ty*8 + i;
        *(float4*)(g_RK + r*512 + by*128 + tx*8)   = make_float4(f0.x, f0.y, f1.x, f1.y);
        *(float4*)(g_RK + r*512 + by*128 + tx*8+4) = make_float4(f2.x, f2.y, f3.x, f3.y);
    }
}

// =================================================================================
// K2: gather + scores + softmax + pooled.  One CTA (128 thr) per batch row.
//   scores[h,k] = (nb_k . rk_h) * 0.125 + log(max(w,1e-6)+1e-6)
//   POOLED[h,:] = sum_k softmax_k * nb_k
// =================================================================================
__global__ void __launch_bounds__(128) k_gather(const float* __restrict__ AE,
                                                const int*   __restrict__ NI,
                                                const float* __restrict__ NW) {
    __shared__ __align__(16) float nbs[16][260];  // gathered neighbor rows
    __shared__ __align__(16) float rks[512];
    __shared__ float sc_s[2][16];
    __shared__ float attn_s[2][16];
    __shared__ int   idx_s[16];

    long b   = blockIdx.x;
    int tid  = threadIdx.x;
    int lane = tid & 31, w = tid >> 5;

    if (tid < 16) idx_s[tid] = NI[b * 16 + tid];
    *(float4*)&rks[tid * 4] = *(const float4*)(g_RK + b * 512 + tid * 4);
    __syncthreads();

    // hoisted rk fragments for this lane's 8 dims
    float4 rA0 = *(float4*)&rks[lane*8];
    float4 rA1 = *(float4*)&rks[lane*8+4];
    float4 rB0 = *(float4*)&rks[256 + lane*8];
    float4 rB1 = *(float4*)&rks[256 + lane*8+4];

    // each warp handles 4 neighbor rows; batch the 8 LDG.128 up front for MLP
    float4 v0[4], v1[4];
    #pragma unroll
    for (int q = 0; q < 4; q++) {
        const float* base = AE + (size_t)idx_s[w*4+q] * 256 + lane * 8;
        v0[q] = *(const float4*)(base);
        v1[q] = *(const float4*)(base + 4);
    }
    #pragma unroll
    for (int q = 0; q < 4; q++) {
        int k = w*4 + q;
        *(float4*)&nbs[k][lane*8]   = v0[q];
        *(float4*)&nbs[k][lane*8+4] = v1[q];
        float s0 = v0[q].x*rA0.x + v0[q].y*rA0.y + v0[q].z*rA0.z + v0[q].w*rA0.w
                 + v1[q].x*rA1.x + v1[q].y*rA1.y + v1[q].z*rA1.z + v1[q].w*rA1.w;
        float s1 = v0[q].x*rB0.x + v0[q].y*rB0.y + v0[q].z*rB0.z + v0[q].w*rB0.w
                 + v1[q].x*rB1.x + v1[q].y*rB1.y + v1[q].z*rB1.z + v1[q].w*rB1.w;
        s0 = wredsum(s0);
        s1 = wredsum(s1);
        if (lane == 0) { sc_s[0][k] = s0; sc_s[1][k] = s1; }
    }
    __syncthreads();

    // softmax over K=16 per head: one lane per (h,k)
    if (tid < 32) {
        int h = tid >> 4, k = tid & 15;
        float lw = NW[b * 16 + k];
        float s = sc_s[h][k] * 0.125f + logf(fmaxf(lw, 1e-6f) + 1e-6f);
        float m = s;
        #pragma unroll
        for (int o = 8; o >= 1; o >>= 1) m = fmaxf(m, __shfl_xor_sync(0xffffffffu, m, o));
        float e = expf(s - m);
        float sum = e;
        #pragma unroll
        for (int o = 8; o >= 1; o >>= 1) sum += __shfl_xor_sync(0xffffffffu, sum, o);
        attn_s[h][k] = e / sum;
    }
    __syncthreads();

    // pooled: thread owns 2 dims
    int d = tid * 2;
    float2 p0 = make_float2(0.f, 0.f), p1 = make_float2(0.f, 0.f);
    #pragma unroll
    for (int k = 0; k < 16; k++) {
        float a0 = attn_s[0][k], a1 = attn_s[1][k];
        float2 v = *(float2*)&nbs[k][d];
        p0.x += a0 * v.x; p0.y += a0 * v.y;
        p1.x += a1 * v.x; p1.y += a1 * v.y;
    }
    *(float2*)(g_PO + b * 512 + d)       = p0;
    *(float2*)(g_PO + b * 512 + 256 + d) = p1;
}

// =================================================================================
// G3:  CTX[b, h*64+j] = sum_d POOLED[b, h*256+d] * Wv[d, h*64+j]   (K=256, N=64)
// grid.y = head. 256 threads, 8x4 register tile.
// =================================================================================
__global__ void __launch_bounds__(256) k_ctx(const float* __restrict__ Wv) {
    __shared__ __align__(16) float As[16][132];
    __shared__ __align__(16) float Bs[16][64];
    int tid = threadIdx.x;
    int tx = tid & 15, ty = tid >> 4;
    long row0 = (long)blockIdx.x * 128;
    int h = blockIdx.y;
    ull acc[8][2];
    #pragma unroll
    for (int i = 0; i < 8; i++) { acc[i][0] = 0ULL; acc[i][1] = 0ULL; }

    for (int k0 = 0; k0 < 256; k0 += 16) {
        #pragma unroll
        for (int it = 0; it < 2; it++) {
            int t = tid + it * 256;
            int r = t >> 2, f = t & 3;
            float4 v = *(const float4*)(g_PO + (row0 + r) * 512 + h * 256 + k0 + f * 4);
            As[f*4+0][r] = v.x; As[f*4+1][r] = v.y; As[f*4+2][r] = v.z; As[f*4+3][r] = v.w;
        }
        {
            int kk = tid >> 4, c = tid & 15;
            *(float4*)&Bs[kk][c*4] = *(const float4*)(Wv + (long)(k0 + kk) * 128 + h * 64 + c * 4);
        }
        __syncthreads();
        #pragma unroll
        for (int kk = 0; kk < 16; kk++) {
            float4 bv = *(float4*)&Bs[kk][tx*4];
            ull bp0 = pk2(bv.x, bv.y), bp1 = pk2(bv.z, bv.w);
            #pragma unroll
            for (int i = 0; i < 8; i++) {
                float a = As[kk][ty*8+i];
                ull a2 = pk2(a, a);
                fma2(acc[i][0], a2, bp0); fma2(acc[i][1], a2, bp1);
            }
        }
        __syncthreads();
    }
    #pragma unroll
    for (int i = 0; i < 8; i++) {
        float2 f0 = up2(acc[i][0]), f1 = up2(acc[i][1]);
        long r = row0 + ty*8 + i;
        *(float4*)(g_CTX + r*128 + h*64 + tx*4) = make_float4(f0.x, f0.y, f1.x, f1.y);
    }
}

// =================================================================================
// G4:  Y = CTX @ Wo  fused with gate / agg / LayerNorm.
// tile 64 rows x 256 cols, each warp owns 8 complete rows (lane covers 8 cols).
// =================================================================================
__global__ void __launch_bounds__(256) k_out(const float* __restrict__ Wo,
                                             const float* __restrict__ Cc,
                                             const float* __restrict__ Wg,
                                             const float* __restrict__ bgp,
                                             const float* __restrict__ gamma,
                                             const float* __restrict__ beta,
                                             float* __restrict__ O) {
    __shared__ __align__(16) float As[16][68];
    __shared__ __align__(16) float Bs[16][256];
    int tid  = threadIdx.x;
    int lane = tid & 31, w = tid >> 5;
    long row0 = (long)blockIdx.x * 64;
    ull acc[8][4];
    #pragma unroll
    for (int i = 0; i < 8; i++)
        #pragma unroll
        for (int j = 0; j < 4; j++) acc[i][j] = 0ULL;

    for (int k0 = 0; k0 < 128; k0 += 16) {
        {
            int r = tid >> 2, f = tid & 3;
            float4 v = *(const float4*)(g_CTX + (row0 + r) * 128 + k0 + f * 4);
            As[f*4+0][r] = v.x; As[f*4+1][r] = v.y; As[f*4+2][r] = v.z; As[f*4+3][r] = v.w;
        }
        #pragma unroll
        for (int it = 0; it < 4; it++) {
            int t = tid + it * 256;
            int kk = t >> 6, c = t & 63;
            *(float4*)&Bs[kk][c*4] = *(const float4*)(Wo + (long)(k0 + kk) * 256 + c * 4);
        }
        __syncthreads();
        #pragma unroll
        for (int kk = 0; kk < 16; kk++) {
            float4 b0 = *(float4*)&Bs[kk][lane*8];
            float4 b1 = *(float4*)&Bs[kk][lane*8+4];
            ull bp0 = pk2(b0.x,b0.y), bp1 = pk2(b0.z,b0.w);
            ull bp2 = pk2(b1.x,b1.y), bp3 = pk2(b1.z,b1.w);
            #pragma unroll
            for (int i = 0; i < 8; i++) {
                float a = As[kk][w*8+i];
                ull a2 = pk2(a, a);
                fma2(acc[i][0], a2, bp0); fma2(acc[i][1], a2, bp1);
                fma2(acc[i][2], a2, bp2); fma2(acc[i][3], a2, bp3);
            }
        }
        __syncthreads();
    }

    // ---- epilogue: gate + agg + LayerNorm, per row within each warp ----
    float4 wg0 = *(const float4*)(Wg + lane*8);
    float4 wg1 = *(const float4*)(Wg + lane*8 + 4);
    float4 wh0 = *(const float4*)(Wg + 256 + lane*8);
    float4 wh1 = *(const float4*)(Wg + 256 + lane*8 + 4);
    float4 gm0 = *(const float4*)(gamma + lane*8);
    float4 gm1 = *(const float4*)(gamma + lane*8 + 4);
    float4 bt0 = *(const float4*)(beta + lane*8);
    float4 bt1 = *(const float4*)(beta + lane*8 + 4);
    float bgv = bgp[0];

    #pragma unroll
    for (int i = 0; i < 8; i++) {
        long gb = row0 + w*8 + i;
        const float* cr = Cc + gb * 256 + lane * 8;
        float4 c0 = *(const float4*)(cr);
        float4 c1 = *(const float4*)(cr + 4);
        float2 u0 = up2(acc[i][0]), u1 = up2(acc[i][1]);
        float2 u2 = up2(acc[i][2]), u3 = up2(acc[i][3]);
        float x[8] = {u0.x,u0.y,u1.x,u1.y,u2.x,u2.y,u3.x,u3.y};
        float cc[8] = {c0.x,c0.y,c0.z,c0.w,c1.x,c1.y,c1.z,c1.w};
        float wgv[8] = {wg0.x,wg0.y,wg0.z,wg0.w,wg1.x,wg1.y,wg1.z,wg1.w};
        float whv[8] = {wh0.x,wh0.y,wh0.z,wh0.w,wh1.x,wh1.y,wh1.z,wh1.w};
        float s = 0.f;
        #pragma unroll
        for (int j = 0; j < 8; j++) s += cc[j]*wgv[j] + x[j]*whv[j];
        s = wredsum(s) + bgv;
        float gate = 1.f / (1.f + expf(-s));
        float a[8], su = 0.f, sq = 0.f;
        #pragma unroll
        for (int j = 0; j < 8; j++) {
            a[j] = gate * cc[j] + (1.f - gate) * x[j];
            su += a[j]; sq += a[j]*a[j];
        }
        su = wredsum(su); sq = wredsum(sq);
        float mu  = su * (1.f/256.f);
        float inv = rsqrtf(sq * (1.f/256.f) - mu*mu + 1e-5f);
        float gv[8] = {gm0.x,gm0.y,gm0.z,gm0.w,gm1.x,gm1.y,gm1.z,gm1.w};
        float bv[8] = {bt0.x,bt0.y,bt0.z,bt0.w,bt1.x,bt1.y,bt1.z,bt1.w};
        float o[8];
        #pragma unroll
        for (int j = 0; j < 8; j++) o[j] = (a[j]-mu)*inv*gv[j] + bv[j];
        *(float4*)(O + gb*256 + lane*8)     = make_float4(o[0],o[1],o[2],o[3]);
        *(float4*)(O + gb*256 + lane*8 + 4) = make_float4(o[4],o[5],o[6],o[7]);
    }
}

// =================================================================================
extern "C" void kernel_launch(void* const* d_in, const int* in_sizes, int n_in,
                              void* d_out, int out_size) {
    const float* C     = (const float*)d_in[0];
    const float* AE    = (const float*)d_in[1];
    const int*   NI    = (const int*)  d_in[2];
    const float* NW    = (const float*)d_in[3];
    const float* Wq    = (const float*)d_in[4];
    const float* Wk    = (const float*)d_in[5];
    const float* Wv    = (const float*)d_in[6];
    const float* Wo    = (const float*)d_in[7];
    const float* Wg    = (const float*)d_in[8];
    const float* bg    = (const float*)d_in[9];
    const float* gamma = (const float*)d_in[10];
    const float* beta  = (const float*)d_in[11];
    float* out = (float*)d_out;

    int B = in_sizes[0] / EMBED_DIM;
    if (B > MAXB) B = MAXB;

    k_q     <<< B / 128, 256 >>>(C, Wq);
    k_rk    <<< dim3(B / 128, 4), 256 >>>(Wk);
    k_gather<<< B, 128 >>>(AE, NI, NW);
    k_ctx   <<< dim3(B / 128, 2), 256 >>>(Wv);
    k_out   <<< B / 64, 256 >>>(Wo, C, Wg, bg, gamma, beta, out);
}

// round 2
// speedup vs baseline: 1.0461x; 1.0461x over previous
#include <cuda_runtime.h>
#include <cuda_bf16.h>
#include <math.h>

// Problem constants
#define EMBED_DIM 256
#define TOTAL_ATTN 128
#define MAXB 32768

typedef unsigned long long ull;

// ---------------- scratch (device globals; no allocation allowed) ----------------
__device__ float g_Q  [(size_t)MAXB * 128];   // q projections      [B,128]
__device__ float g_RK [(size_t)MAXB * 512];   // rk = Wk_h q_h      [B,2,256]
__device__ float g_PO [(size_t)MAXB * 512];   // attn-pooled nb     [B,2,256]
__device__ float g_CTX[(size_t)MAXB * 128];   // ctx (pre-Wo)       [B,128]

// ---------------- f32x2 helpers (packed FMA: 2x fp32 throughput) ----------------
__device__ __forceinline__ ull pk2(float x, float y) {
    ull r; asm("mov.b64 %0, {%1, %2};" : "=l"(r) : "f"(x), "f"(y)); return r;
}
__device__ __forceinline__ void fma2(ull &d, ull a, ull b) {
    asm("fma.rn.f32x2 %0, %1, %2, %0;" : "+l"(d) : "l"(a), "l"(b));
}
__device__ __forceinline__ float2 up2(ull v) {
    float2 r; asm("mov.b64 {%0, %1}, %2;" : "=f"(r.x), "=f"(r.y) : "l"(v)); return r;
}
__device__ __forceinline__ float wredsum(float v) {
    #pragma unroll
    for (int o = 16; o >= 1; o >>= 1) v += __shfl_xor_sync(0xffffffffu, v, o);
    return v;
}

// =================================================================================
// G1:  Q[B,128] = C[B,256] @ Wq[256,128]
// tile 128x128, K=256 in 16 chunks, software-pipelined (reg prefetch).
// =================================================================================
__global__ void __launch_bounds__(256) k_q(const float* __restrict__ A,
                                           const float* __restrict__ W) {
    __shared__ __align__(16) float As[16][132];  // [kk][row]
    __shared__ __align__(16) float Bs[16][128];
    int tid = threadIdx.x;
    int tx = tid & 15, ty = tid >> 4;
    long row0 = (long)blockIdx.x * 128;
    ull acc[8][4];
    #pragma unroll
    for (int i = 0; i < 8; i++)
        #pragma unroll
        for (int j = 0; j < 4; j++) acc[i][j] = 0ULL;

    int ra = tid >> 2, fa = tid & 3;          // A-load coords (x2 via it)
    float4 pa[2], pb[2];

    // prefetch chunk 0
    #pragma unroll
    for (int it = 0; it < 2; it++) {
        int t = tid + it * 256;
        int r = t >> 2, f = t & 3;
        pa[it] = *(const float4*)(A + (row0 + r) * 256 + f * 4);
        int kk = t >> 5, c = t & 31;
        pb[it] = *(const float4*)(W + (long)kk * 128 + c * 4);
    }

    for (int ch = 0; ch < 16; ch++) {
        __syncthreads();
        #pragma unroll
        for (int it = 0; it < 2; it++) {
            int t = tid + it * 256;
            int r = t >> 2, f = t & 3;
            As[f*4+0][r] = pa[it].x; As[f*4+1][r] = pa[it].y;
            As[f*4+2][r] = pa[it].z; As[f*4+3][r] = pa[it].w;
            int kk = t >> 5, c = t & 31;
            *(float4*)&Bs[kk][c*4] = pb[it];
        }
        __syncthreads();
        if (ch < 15) {
            int k0 = (ch + 1) * 16;
            #pragma unroll
            for (int it = 0; it < 2; it++) {
                int t = tid + it * 256;
                int r = t >> 2, f = t & 3;
                pa[it] = *(const float4*)(A + (row0 + r) * 256 + k0 + f * 4);
                int kk = t >> 5, c = t & 31;
                pb[it] = *(const float4*)(W + (long)(k0 + kk) * 128 + c * 4);
            }
        }
        #pragma unroll
        for (int kk = 0; kk < 16; kk++) {
            float4 b0 = *(float4*)&Bs[kk][tx*8];
            float4 b1 = *(float4*)&Bs[kk][tx*8+4];
            ull bp0 = pk2(b0.x,b0.y), bp1 = pk2(b0.z,b0.w);
            ull bp2 = pk2(b1.x,b1.y), bp3 = pk2(b1.z,b1.w);
            #pragma unroll
            for (int i = 0; i < 8; i++) {
                float a = As[kk][ty*8+i];
                ull a2 = pk2(a, a);
                fma2(acc[i][0], a2, bp0); fma2(acc[i][1], a2, bp1);
                fma2(acc[i][2], a2, bp2); fma2(acc[i][3], a2, bp3);
            }
        }
    }
    (void)ra; (void)fa;
    #pragma unroll
    for (int i = 0; i < 8; i++) {
        float2 f0 = up2(acc[i][0]), f1 = up2(acc[i][1]);
        float2 f2 = up2(acc[i][2]), f3 = up2(acc[i][3]);
        long r = row0 + ty*8 + i;
        *(float4*)(g_Q + r*128 + tx*8)   = make_float4(f0.x, f0.y, f1.x, f1.y);
        *(float4*)(g_Q + r*128 + tx*8+4) = make_float4(f2.x, f2.y, f3.x, f3.y);
    }
}

// =================================================================================
// G2:  RK[b, by*128+d'] = sum_j Q[b, h*64+j] * Wk[d0+d', h*64+j]   (K=64, pipelined)
// =================================================================================
__global__ void __launch_bounds__(256) k_rk(const float* __restrict__ Wk) {
    __shared__ __align__(16) float As[16][132];
    __shared__ __align__(16) float Bs[16][132];
    int tid = threadIdx.x;
    int tx = tid & 15, ty = tid >> 4;
    long row0 = (long)blockIdx.x * 128;
    int by = blockIdx.y;
    int h = by >> 1, d0 = (by & 1) * 128;
    ull acc[8][4];
    #pragma unroll
    for (int i = 0; i < 8; i++)
        #pragma unroll
        for (int j = 0; j < 4; j++) acc[i][j] = 0ULL;

    float4 pa[2], pb[2];
    #pragma unroll
    for (int it = 0; it < 2; it++) {
        int t = tid + it * 256;
        int r = t >> 2, f = t & 3;
        pa[it] = *(const float4*)(g_Q + (row0 + r) * 128 + h * 64 + f * 4);
        pb[it] = *(const float4*)(Wk + (long)(d0 + r) * 128 + h * 64 + f * 4);
    }

    for (int ch = 0; ch < 4; ch++) {
        __syncthreads();
        #pragma unroll
        for (int it = 0; it < 2; it++) {
            int t = tid + it * 256;
            int r = t >> 2, f = t & 3;
            As[f*4+0][r] = pa[it].x; As[f*4+1][r] = pa[it].y;
            As[f*4+2][r] = pa[it].z; As[f*4+3][r] = pa[it].w;
            Bs[f*4+0][r] = pb[it].x; Bs[f*4+1][r] = pb[it].y;
            Bs[f*4+2][r] = pb[it].z; Bs[f*4+3][r] = pb[it].w;
        }
        __syncthreads();
        if (ch < 3) {
            int k0 = (ch + 1) * 16;
            #pragma unroll
            for (int it = 0; it < 2; it++) {
                int t = tid + it * 256;
                int r = t >> 2, f = t & 3;
                pa[it] = *(const float4*)(g_Q + (row0 + r) * 128 + h * 64 + k0 + f * 4);
                pb[it] = *(const float4*)(Wk + (long)(d0 + r) * 128 + h * 64 + k0 + f * 4);
            }
        }
        #pragma unroll
        for (int kk = 0; kk < 16; kk++) {
            float4 b0 = *(float4*)&Bs[kk][tx*8];
            float4 b1 = *(float4*)&Bs[kk][tx*8+4];
            ull bp0 = pk2(b0.x,b0.y), bp1 = pk2(b0.z,b0.w);
            ull bp2 = pk2(b1.x,b1.y), bp3 = pk2(b1.z,b1.w);
            #pragma unroll
            for (int i = 0; i < 8; i++) {
                float a = As[kk][ty*8+i];
                ull a2 = pk2(a, a);
                fma2(acc[i][0], a2, bp0); fma2(acc[i][1], a2, bp1);
                fma2(acc[i][2], a2, bp2); fma2(acc[i][3], a2, bp3);
            }
        }
    }
    #pragma unroll
    for (int i = 0; i < 8; i++) {
        float2 f0 = up2(acc[i][0]), f1 = up2(acc[i][1]);
        float2 f2 = up2(acc[i][2]), f3 = up2(acc[i][3]);
        long r = row0 + ty*8 + i;
        *(float4*)(g_RK + r*512 + by*128 + tx*8)   = make_float4(f0.x, f0.y, f1.x, f1.y);
        *(float4*)(g_RK + r*512 + by*128 + tx*8+4) = make_float4(f2.x, f2.y, f3.x, f3.y);
    }
}

// =================================================================================
// K2: gather + scores + softmax + pooled. One CTA (128 thr) per batch row.
// Neighbor rows stay in registers; cross-warp pool reduced through 8KB smem.
// =================================================================================
__global__ void __launch_bounds__(128) k_gather(const float* __restrict__ AE,
                                                const int*   __restrict__ NI,
                                                const float* __restrict__ NW) {
    __shared__ float sc_s[2][16];
    __shared__ float attn_s[2][16];
    __shared__ __align__(16) float red[4][512];

    long b   = blockIdx.x;
    int tid  = threadIdx.x;
    int lane = tid & 31, w = tid >> 5;

    // per-lane rk fragments (broadcast across warps, L1-resident)
    const float* rkb = g_RK + b * 512;
    float4 rA0 = *(const float4*)(rkb + lane*8);
    float4 rA1 = *(const float4*)(rkb + lane*8 + 4);
    float4 rB0 = *(const float4*)(rkb + 256 + lane*8);
    float4 rB1 = *(const float4*)(rkb + 256 + lane*8 + 4);

    // neighbor indices for this warp's 4 rows (broadcast LDGs)
    int idx[4];
    #pragma unroll
    for (int q = 0; q < 4; q++) idx[q] = __ldg(NI + b * 16 + w * 4 + q);

    // batch the 8 LDG.128 gathers
    float4 v0[4], v1[4];
    #pragma unroll
    for (int q = 0; q < 4; q++) {
        const float* base = AE + (size_t)idx[q] * 256 + lane * 8;
        v0[q] = *(const float4*)(base);
        v1[q] = *(const float4*)(base + 4);
    }

    // scores per row (warp reduction over 256 dims)
    #pragma unroll
    for (int q = 0; q < 4; q++) {
        int k = w*4 + q;
        float s0 = v0[q].x*rA0.x + v0[q].y*rA0.y + v0[q].z*rA0.z + v0[q].w*rA0.w
                 + v1[q].x*rA1.x + v1[q].y*rA1.y + v1[q].z*rA1.z + v1[q].w*rA1.w;
        float s1 = v0[q].x*rB0.x + v0[q].y*rB0.y + v0[q].z*rB0.z + v0[q].w*rB0.w
                 + v1[q].x*rB1.x + v1[q].y*rB1.y + v1[q].z*rB1.z + v1[q].w*rB1.w;
        s0 = wredsum(s0);
        s1 = wredsum(s1);
        if (lane == 0) { sc_s[0][k] = s0; sc_s[1][k] = s1; }
    }
    __syncthreads();

    // softmax over K=16 per head (warp 0, one lane per (h,k))
    if (tid < 32) {
        int h = tid >> 4, k = tid & 15;
        float lw = NW[b * 16 + k];
        float s = sc_s[h][k] * 0.125f + logf(fmaxf(lw, 1e-6f) + 1e-6f);
        float m = s;
        #pragma unroll
        for (int o = 8; o >= 1; o >>= 1) m = fmaxf(m, __shfl_xor_sync(0xffffffffu, m, o));
        float e = expf(s - m);
        float sum = e;
        #pragma unroll
        for (int o = 8; o >= 1; o >>= 1) sum += __shfl_xor_sync(0xffffffffu, sum, o);
        attn_s[h][k] = e / sum;
    }
    __syncthreads();

    // per-warp partial pools over this warp's 4 rows (register resident)
    float pA[8] = {0,0,0,0,0,0,0,0};
    float pB[8] = {0,0,0,0,0,0,0,0};
    #pragma unroll
    for (int q = 0; q < 4; q++) {
        float a0 = attn_s[0][w*4+q], a1 = attn_s[1][w*4+q];
        float vv[8] = {v0[q].x,v0[q].y,v0[q].z,v0[q].w,v1[q].x,v1[q].y,v1[q].z,v1[q].w};
        #pragma unroll
        for (int j = 0; j < 8; j++) { pA[j] += a0 * vv[j]; pB[j] += a1 * vv[j]; }
    }
    *(float4*)&red[w][lane*8]         = make_float4(pA[0],pA[1],pA[2],pA[3]);
    *(float4*)&red[w][lane*8+4]       = make_float4(pA[4],pA[5],pA[6],pA[7]);
    *(float4*)&red[w][256+lane*8]     = make_float4(pB[0],pB[1],pB[2],pB[3]);
    *(float4*)&red[w][256+lane*8+4]   = make_float4(pB[4],pB[5],pB[6],pB[7]);
    __syncthreads();

    // cross-warp reduce (each thread: 4 contiguous dims of the 512)
    float4 r0 = *(float4*)&red[0][tid*4];
    float4 r1 = *(float4*)&red[1][tid*4];
    float4 r2 = *(float4*)&red[2][tid*4];
    float4 r3 = *(float4*)&red[3][tid*4];
    float4 o;
    o.x = r0.x + r1.x + r2.x + r3.x;
    o.y = r0.y + r1.y + r2.y + r3.y;
    o.z = r0.z + r1.z + r2.z + r3.z;
    o.w = r0.w + r1.w + r2.w + r3.w;
    *(float4*)(g_PO + b * 512 + tid * 4) = o;
}

// =================================================================================
// G3:  CTX[b, h*64+j] = sum_d PO[b, h*256+d] * Wv[d, h*64+j]
// Both heads merged: tile 128 rows x 128 cols (col half = head), K=256, pipelined.
// B operand is the full 128-wide Wv row; A differs per column-half.
// =================================================================================
__global__ void __launch_bounds__(256) k_ctx(const float* __restrict__ Wv) {
    __shared__ __align__(16) float As[2][16][132];
    __shared__ __align__(16) float Bs[16][128];
    int tid = threadIdx.x;
    int tx = tid & 15, ty = tid >> 4;
    int hh = tx >> 3;                       // this thread's head (column half)
    long row0 = (long)blockIdx.x * 128;
    ull acc[8][4];
    #pragma unroll
    for (int i = 0; i < 8; i++)
        #pragma unroll
        for (int j = 0; j < 4; j++) acc[i][j] = 0ULL;

    float4 pa[4], pb[2];
    #pragma unroll
    for (int it = 0; it < 4; it++) {
        int t = tid + it * 256;             // 0..1023
        int hdr = t >> 9, r = (t >> 2) & 127, f = t & 3;
        pa[it] = *(const float4*)(g_PO + (row0 + r) * 512 + hdr * 256 + f * 4);
    }
    #pragma unroll
    for (int it = 0; it < 2; it++) {
        int t = tid + it * 256;
        int kk = t >> 5, c = t & 31;
        pb[it] = *(const float4*)(Wv + (long)kk * 128 + c * 4);
    }

    for (int ch = 0; ch < 16; ch++) {
        __syncthreads();
        #pragma unroll
        for (int it = 0; it < 4; it++) {
            int t = tid + it * 256;
            int hdr = t >> 9, r = (t >> 2) & 127, f = t & 3;
            As[hdr][f*4+0][r] = pa[it].x; As[hdr][f*4+1][r] = pa[it].y;
            As[hdr][f*4+2][r] = pa[it].z; As[hdr][f*4+3][r] = pa[it].w;
        }
        #pragma unroll
        for (int it = 0; it < 2; it++) {
            int t = tid + it * 256;
            int kk = t >> 5, c = t & 31;
            *(float4*)&Bs[kk][c*4] = pb[it];
        }
        __syncthreads();
        if (ch < 15) {
            int k0 = (ch + 1) * 16;
            #pragma unroll
            for (int it = 0; it < 4; it++) {
                int t = tid + it * 256;
                int hdr = t >> 9, r = (t >> 2) & 127, f = t & 3;
                pa[it] = *(const float4*)(g_PO + (row0 + r) * 512 + hdr * 256 + k0 + f * 4);
            }
            #pragma unroll
            for (int it = 0; it < 2; it++) {
                int t = tid + it * 256;
                int kk = t >> 5, c = t & 31;
                pb[it] = *(const float4*)(Wv + (long)(k0 + kk) * 128 + c * 4);
            }
        }
        #pragma unroll
        for (int kk = 0; kk < 16; kk++) {
            float4 b0 = *(float4*)&Bs[kk][tx*8];
            float4 b1 = *(float4*)&Bs[kk][tx*8+4];
            ull bp0 = pk2(b0.x,b0.y), bp1 = pk2(b0.z,b0.w);
            ull bp2 = pk2(b1.x,b1.y), bp3 = pk2(b1.z,b1.w);
            #pragma unroll
            for (int i = 0; i < 8; i++) {
                float a = As[hh][kk][ty*8+i];
                ull a2 = pk2(a, a);
                fma2(acc[i][0], a2, bp0); fma2(acc[i][1], a2, bp1);
                fma2(acc[i][2], a2, bp2); fma2(acc[i][3], a2, bp3);
            }
        }
    }
    #pragma unroll
    for (int i = 0; i < 8; i++) {
        float2 f0 = up2(acc[i][0]), f1 = up2(acc[i][1]);
        float2 f2 = up2(acc[i][2]), f3 = up2(acc[i][3]);
        long r = row0 + ty*8 + i;
        *(float4*)(g_CTX + r*128 + tx*8)   = make_float4(f0.x, f0.y, f1.x, f1.y);
        *(float4*)(g_CTX + r*128 + tx*8+4) = make_float4(f2.x, f2.y, f3.x, f3.y);
    }
}

// =================================================================================
// G4:  Y = CTX @ Wo  fused with gate / agg / LayerNorm.  K=128, pipelined.
// tile 64 rows x 256 cols; warp owns 8 full rows (lane covers 8 cols).
// =================================================================================
__global__ void __launch_bounds__(256) k_out(const float* __restrict__ Wo,
                                             const float* __restrict__ Cc,
                                             const float* __restrict__ Wg,
                                             const float* __restrict__ bgp,
                                             const float* __restrict__ gamma,
                                             const float* __restrict__ beta,
                                             float* __restrict__ O) {
    __shared__ __align__(16) float As[16][68];
    __shared__ __align__(16) float Bs[16][256];
    int tid  = threadIdx.x;
    int lane = tid & 31, w = tid >> 5;
    long row0 = (long)blockIdx.x * 64;
    ull acc[8][4];
    #pragma unroll
    for (int i = 0; i < 8; i++)
        #pragma unroll
        for (int j = 0; j < 4; j++) acc[i][j] = 0ULL;

    float4 pa, pb[4];
    {
        int r = tid >> 2, f = tid & 3;
        pa = *(const float4*)(g_CTX + (row0 + r) * 128 + f * 4);
        #pragma unroll
        for (int it = 0; it < 4; it++) {
            int t = tid + it * 256;
            int kk = t >> 6, c = t & 63;
            pb[it] = *(const float4*)(Wo + (long)kk * 256 + c * 4);
        }
    }

    for (int ch = 0; ch < 8; ch++) {
        __syncthreads();
        {
            int r = tid >> 2, f = tid & 3;
            As[f*4+0][r] = pa.x; As[f*4+1][r] = pa.y;
            As[f*4+2][r] = pa.z; As[f*4+3][r] = pa.w;
        }
        #pragma unroll
        for (int it = 0; it < 4; it++) {
            int t = tid + it * 256;
            int kk = t >> 6, c = t & 63;
            *(float4*)&Bs[kk][c*4] = pb[it];
        }
        __syncthreads();
        if (ch < 7) {
            int k0 = (ch + 1) * 16;
            int r = tid >> 2, f = tid & 3;
            pa = *(const float4*)(g_CTX + (row0 + r) * 128 + k0 + f * 4);
            #pragma unroll
            for (int it = 0; it < 4; it++) {
                int t = tid + it * 256;
                int kk = t >> 6, c = t & 63;
                pb[it] = *(const float4*)(Wo + (long)(k0 + kk) * 256 + c * 4);
            }
        }
        #pragma unroll
        for (int kk = 0; kk < 16; kk++) {
            float4 b0 = *(float4*)&Bs[kk][lane*8];
            float4 b1 = *(float4*)&Bs[kk][lane*8+4];
            ull bp0 = pk2(b0.x,b0.y), bp1 = pk2(b0.z,b0.w);
            ull bp2 = pk2(b1.x,b1.y), bp3 = pk2(b1.z,b1.w);
            #pragma unroll
            for (int i = 0; i < 8; i++) {
                float a = As[kk][w*8+i];
                ull a2 = pk2(a, a);
                fma2(acc[i][0], a2, bp0); fma2(acc[i][1], a2, bp1);
                fma2(acc[i][2], a2, bp2); fma2(acc[i][3], a2, bp3);
            }
        }
    }

    // ---- epilogue: gate + agg + LayerNorm, per row within each warp ----
    float4 wg0 = *(const float4*)(Wg + lane*8);
    float4 wg1 = *(const float4*)(Wg + lane*8 + 4);
    float4 wh0 = *(const float4*)(Wg + 256 + lane*8);
    float4 wh1 = *(const float4*)(Wg + 256 + lane*8 + 4);
    float4 gm0 = *(const float4*)(gamma + lane*8);
    float4 gm1 = *(const float4*)(gamma + lane*8 + 4);
    float4 bt0 = *(const float4*)(beta + lane*8);
    float4 bt1 = *(const float4*)(beta + lane*8 + 4);
    float bgv = bgp[0];

    #pragma unroll
    for (int i = 0; i < 8; i++) {
        long gb = row0 + w*8 + i;
        const float* cr = Cc + gb * 256 + lane * 8;
        float4 c0 = *(const float4*)(cr);
        float4 c1 = *(const float4*)(cr + 4);
        float2 u0 = up2(acc[i][0]), u1 = up2(acc[i][1]);
        float2 u2 = up2(acc[i][2]), u3 = up2(acc[i][3]);
        float x[8] = {u0.x,u0.y,u1.x,u1.y,u2.x,u2.y,u3.x,u3.y};
        float cc[8] = {c0.x,c0.y,c0.z,c0.w,c1.x,c1.y,c1.z,c1.w};
        float wgv[8] = {wg0.x,wg0.y,wg0.z,wg0.w,wg1.x,wg1.y,wg1.z,wg1.w};
        float whv[8] = {wh0.x,wh0.y,wh0.z,wh0.w,wh1.x,wh1.y,wh1.z,wh1.w};
        float s = 0.f;
        #pragma unroll
        for (int j = 0; j < 8; j++) s += cc[j]*wgv[j] + x[j]*whv[j];
        s = wredsum(s) + bgv;
        float gate = 1.f / (1.f + expf(-s));
        float a[8], su = 0.f, sq = 0.f;
        #pragma unroll
        for (int j = 0; j < 8; j++) {
            a[j] = gate * cc[j] + (1.f - gate) * x[j];
            su += a[j]; sq += a[j]*a[j];
        }
        su = wredsum(su); sq = wredsum(sq);
        float mu  = su * (1.f/256.f);
        float inv = rsqrtf(sq * (1.f/256.f) - mu*mu + 1e-5f);
        float gv[8] = {gm0.x,gm0.y,gm0.z,gm0.w,gm1.x,gm1.y,gm1.z,gm1.w};
        float bv[8] = {bt0.x,bt0.y,bt0.z,bt0.w,bt1.x,bt1.y,bt1.z,bt1.w};
        float o[8];
        #pragma unroll
        for (int j = 0; j < 8; j++) o[j] = (a[j]-mu)*inv*gv[j] + bv[j];
        *(float4*)(O + gb*256 + lane*8)     = make_float4(o[0],o[1],o[2],o[3]);
        *(float4*)(O + gb*256 + lane*8 + 4) = make_float4(o[4],o[5],o[6],o[7]);
    }
}

// =================================================================================
extern "C" void kernel_launch(void* const* d_in, const int* in_sizes, int n_in,
                              void* d_out, int out_size) {
    const float* C     = (const float*)d_in[0];
    const float* AE    = (const float*)d_in[1];
    const int*   NI    = (const int*)  d_in[2];
    const float* NW    = (const float*)d_in[3];
    const float* Wq    = (const float*)d_in[4];
    const float* Wk    = (const float*)d_in[5];
    const float* Wv    = (const float*)d_in[6];
    const float* Wo    = (const float*)d_in[7];
    const float* Wg    = (const float*)d_in[8];
    const float* bg    = (const float*)d_in[9];
    const float* gamma = (const float*)d_in[10];
    const float* beta  = (const float*)d_in[11];
    float* out = (float*)d_out;

    int B = in_sizes[0] / EMBED_DIM;
    if (B > MAXB) B = MAXB;

    k_q     <<< B / 128, 256 >>>(C, Wq);
    k_rk    <<< dim3(B / 128, 4), 256 >>>(Wk);
    k_gather<<< B, 128 >>>(AE, NI, NW);
    k_ctx   <<< B / 128, 256 >>>(Wv);
    k_out   <<< B / 64, 256 >>>(Wo, C, Wg, bg, gamma, beta, out);
}

// round 3
// speedup vs baseline: 1.0672x; 1.0202x over previous
#include <cuda_runtime.h>
#include <cuda_bf16.h>
#include <math.h>

#define EMBED_DIM 256
#define MAXB 32768

typedef unsigned long long ull;

// ---------------- scratch (device globals; no allocation allowed) ----------------
__device__ float g_RK [(size_t)MAXB * 512];   // rk = Wk_h q_h      [B,2,256]
__device__ float g_PO [(size_t)MAXB * 512];   // attn-pooled nb     [B,2,256]
__device__ float g_WkT[128 * 256];            // Wk transposed [j][d]

// ---------------- f32x2 helpers ----------------
__device__ __forceinline__ ull pk2(float x, float y) {
    ull r; asm("mov.b64 %0, {%1, %2};" : "=l"(r) : "f"(x), "f"(y)); return r;
}
__device__ __forceinline__ void fma2(ull &d, ull a, ull b) {
    asm("fma.rn.f32x2 %0, %1, %2, %0;" : "+l"(d) : "l"(a), "l"(b));
}
__device__ __forceinline__ float2 up2(ull v) {
    float2 r; asm("mov.b64 {%0, %1}, %2;" : "=f"(r.x), "=f"(r.y) : "l"(v)); return r;
}
__device__ __forceinline__ float wredsum(float v) {
    #pragma unroll
    for (int o = 16; o >= 1; o >>= 1) v += __shfl_xor_sync(0xffffffffu, v, o);
    return v;
}

// ---------------- cp.async helpers ----------------
__device__ __forceinline__ unsigned s2u(const void* p) {
    return (unsigned)__cvta_generic_to_shared(p);
}
__device__ __forceinline__ void cpa(unsigned s, const void* g) {
    asm volatile("cp.async.cg.shared.global [%0], [%1], 16;" :: "r"(s), "l"(g) : "memory");
}
__device__ __forceinline__ void cpc() {
    asm volatile("cp.async.commit_group;" ::: "memory");
}
template<int N> __device__ __forceinline__ void cpw() {
    asm volatile("cp.async.wait_group %0;" :: "n"(N) : "memory");
}

// =================================================================================
// k_tr: g_WkT[j][d] = Wk[d][j]    (128x256 <- 256x128)
// =================================================================================
__global__ void __launch_bounds__(256) k_tr(const float* __restrict__ Wk) {
    int idx = blockIdx.x * 256 + threadIdx.x;   // 0..32767
    int j = idx >> 8, d = idx & 255;
    g_WkT[j * 256 + d] = Wk[d * 128 + j];
}

// =================================================================================
// k_qrk: fused  Q = C@Wq  (tile 128x128, K=256)  then  RK = Q_h @ Wk_h^T
// smem (floats): AsRM [2][128][20] @0 | Bs [2][16][128] @5120 | Qs [128][132] @9216
// total 26112 floats = 104448 B dynamic
// =================================================================================
#define QRK_SMEM_BYTES (26112 * 4)

__global__ void __launch_bounds__(256, 2) k_qrk(const float* __restrict__ C,
                                                const float* __restrict__ Wq) {
    extern __shared__ float sm[];
    float* AsRM = sm;            // [buf][r(128)][kpad20]
    float* Bs   = sm + 5120;     // [buf][kk(16)][128]
    float* Qs   = sm + 9216;     // [r(128)][132]
    int tid = threadIdx.x;
    int tx = tid & 15, ty = tid >> 4;
    long row0 = (long)blockIdx.x * 128;

    ull acc[8][4];
    #pragma unroll
    for (int i = 0; i < 8; i++)
        #pragma unroll
        for (int j = 0; j < 4; j++) acc[i][j] = 0ULL;

    // ---------------- stage 1: Q tile ----------------
    auto issue1 = [&](int ch, int buf) {
        int k0 = ch * 16;
        #pragma unroll
        for (int it = 0; it < 2; it++) {
            int t = tid + it * 256;
            int r = t >> 2, f = t & 3;
            cpa(s2u(&AsRM[buf*2560 + r*20 + f*4]), C + (row0 + r)*256 + k0 + f*4);
        }
        #pragma unroll
        for (int it = 0; it < 2; it++) {
            int t = tid + it * 256;
            int kk = t >> 5, c = (t & 31) * 4;
            cpa(s2u(&Bs[buf*2048 + kk*128 + c]), Wq + (long)(k0 + kk)*128 + c);
        }
        cpc();
    };

    issue1(0, 0);
    int buf = 0;
    for (int ch = 0; ch < 16; ch++) {
        if (ch + 1 < 16) { issue1(ch + 1, buf ^ 1); cpw<1>(); } else { cpw<0>(); }
        __syncthreads();
        const float* bb = &Bs[buf*2048];
        const float* aa = &AsRM[buf*2560];
        #pragma unroll
        for (int kk = 0; kk < 16; kk++) {
            float4 b0 = *(const float4*)&bb[kk*128 + tx*8];
            float4 b1 = *(const float4*)&bb[kk*128 + tx*8 + 4];
            ull bp0 = pk2(b0.x,b0.y), bp1 = pk2(b0.z,b0.w);
            ull bp2 = pk2(b1.x,b1.y), bp3 = pk2(b1.z,b1.w);
            #pragma unroll
            for (int i = 0; i < 8; i++) {
                float a = aa[(ty*8+i)*20 + kk];
                ull a2 = pk2(a, a);
                fma2(acc[i][0], a2, bp0); fma2(acc[i][1], a2, bp1);
                fma2(acc[i][2], a2, bp2); fma2(acc[i][3], a2, bp3);
            }
        }
        __syncthreads();
        buf ^= 1;
    }

    // stage-1 epilogue: stage Q tile into smem (row-major, pad 132)
    #pragma unroll
    for (int i = 0; i < 8; i++) {
        float2 f0 = up2(acc[i][0]), f1 = up2(acc[i][1]);
        float2 f2 = up2(acc[i][2]), f3 = up2(acc[i][3]);
        int r = ty*8 + i;
        *(float4*)&Qs[r*132 + tx*8]     = make_float4(f0.x, f0.y, f1.x, f1.y);
        *(float4*)&Qs[r*132 + tx*8 + 4] = make_float4(f2.x, f2.y, f3.x, f3.y);
    }
    __syncthreads();

    // ---------------- stage 2: RK = Q_h @ Wk_h^T  (4 col-chunks of 128, K=64) ----------------
    auto issue2 = [&](int g, int b2) {
        int cc = g >> 2, kc = g & 3;
        int h = cc >> 1, d0 = (cc & 1) * 128;
        int j0 = h*64 + kc*16;
        #pragma unroll
        for (int it = 0; it < 2; it++) {
            int t = tid + it * 256;
            int kk = t >> 5, c = (t & 31) * 4;
            cpa(s2u(&Bs[b2*2048 + kk*128 + c]), g_WkT + (j0 + kk)*256 + d0 + c);
        }
        cpc();
    };

    issue2(0, 0);
    buf = 0;
    for (int g = 0; g < 16; g++) {
        int cc = g >> 2, kc = g & 3;
        int h = cc >> 1;
        if ((g & 3) == 0) {
            #pragma unroll
            for (int i = 0; i < 8; i++)
                #pragma unroll
                for (int j = 0; j < 4; j++) acc[i][j] = 0ULL;
        }
        if (g + 1 < 16) { issue2(g + 1, buf ^ 1); cpw<1>(); } else { cpw<0>(); }
        __syncthreads();
        const float* bb = &Bs[buf*2048];
        int j0 = h*64 + kc*16;
        #pragma unroll
        for (int kk = 0; kk < 16; kk++) {
            float4 b0 = *(const float4*)&bb[kk*128 + tx*8];
            float4 b1 = *(const float4*)&bb[kk*128 + tx*8 + 4];
            ull bp0 = pk2(b0.x,b0.y), bp1 = pk2(b0.z,b0.w);
            ull bp2 = pk2(b1.x,b1.y), bp3 = pk2(b1.z,b1.w);
            #pragma unroll
            for (int i = 0; i < 8; i++) {
                float a = Qs[(ty*8+i)*132 + j0 + kk];
                ull a2 = pk2(a, a);
                fma2(acc[i][0], a2, bp0); fma2(acc[i][1], a2, bp1);
                fma2(acc[i][2], a2, bp2); fma2(acc[i][3], a2, bp3);
            }
        }
        __syncthreads();
        if ((g & 3) == 3) {
            #pragma unroll
            for (int i = 0; i < 8; i++) {
                float2 f0 = up2(acc[i][0]), f1 = up2(acc[i][1]);
                float2 f2 = up2(acc[i][2]), f3 = up2(acc[i][3]);
                long r = row0 + ty*8 + i;
                *(float4*)(g_RK + r*512 + cc*128 + tx*8)     = make_float4(f0.x, f0.y, f1.x, f1.y);
                *(float4*)(g_RK + r*512 + cc*128 + tx*8 + 4) = make_float4(f2.x, f2.y, f3.x, f3.y);
            }
        }
        buf ^= 1;
    }
}

// =================================================================================
// k_gather: gather + scores + softmax + pooled. One CTA (128 thr) per batch row.
// =================================================================================
__global__ void __launch_bounds__(128) k_gather(const float* __restrict__ AE,
                                                const int*   __restrict__ NI,
                                                const float* __restrict__ NW) {
    __shared__ float sc_s[2][16];
    __shared__ float attn_s[2][16];
    __shared__ __align__(16) float red[4][512];

    long b   = blockIdx.x;
    int tid  = threadIdx.x;
    int lane = tid & 31, w = tid >> 5;

    const float* rkb = g_RK + b * 512;
    float4 rA0 = *(const float4*)(rkb + lane*8);
    float4 rA1 = *(const float4*)(rkb + lane*8 + 4);
    float4 rB0 = *(const float4*)(rkb + 256 + lane*8);
    float4 rB1 = *(const float4*)(rkb + 256 + lane*8 + 4);

    int idx[4];
    #pragma unroll
    for (int q = 0; q < 4; q++) idx[q] = __ldg(NI + b * 16 + w * 4 + q);

    float4 v0[4], v1[4];
    #pragma unroll
    for (int q = 0; q < 4; q++) {
        const float* base = AE + (size_t)idx[q] * 256 + lane * 8;
        v0[q] = *(const float4*)(base);
        v1[q] = *(const float4*)(base + 4);
    }

    #pragma unroll
    for (int q = 0; q < 4; q++) {
        int k = w*4 + q;
        float s0 = v0[q].x*rA0.x + v0[q].y*rA0.y + v0[q].z*rA0.z + v0[q].w*rA0.w
                 + v1[q].x*rA1.x + v1[q].y*rA1.y + v1[q].z*rA1.z + v1[q].w*rA1.w;
        float s1 = v0[q].x*rB0.x + v0[q].y*rB0.y + v0[q].z*rB0.z + v0[q].w*rB0.w
                 + v1[q].x*rB1.x + v1[q].y*rB1.y + v1[q].z*rB1.z + v1[q].w*rB1.w;
        s0 = wredsum(s0);
        s1 = wredsum(s1);
        if (lane == 0) { sc_s[0][k] = s0; sc_s[1][k] = s1; }
    }
    __syncthreads();

    if (tid < 32) {
        int h = tid >> 4, k = tid & 15;
        float lw = NW[b * 16 + k];
        float s = sc_s[h][k] * 0.125f + logf(fmaxf(lw, 1e-6f) + 1e-6f);
        float m = s;
        #pragma unroll
        for (int o = 8; o >= 1; o >>= 1) m = fmaxf(m, __shfl_xor_sync(0xffffffffu, m, o));
        float e = expf(s - m);
        float sum = e;
        #pragma unroll
        for (int o = 8; o >= 1; o >>= 1) sum += __shfl_xor_sync(0xffffffffu, sum, o);
        attn_s[h][k] = e / sum;
    }
    __syncthreads();

    float pA[8] = {0,0,0,0,0,0,0,0};
    float pB[8] = {0,0,0,0,0,0,0,0};
    #pragma unroll
    for (int q = 0; q < 4; q++) {
        float a0 = attn_s[0][w*4+q], a1 = attn_s[1][w*4+q];
        float vv[8] = {v0[q].x,v0[q].y,v0[q].z,v0[q].w,v1[q].x,v1[q].y,v1[q].z,v1[q].w};
        #pragma unroll
        for (int j = 0; j < 8; j++) { pA[j] += a0 * vv[j]; pB[j] += a1 * vv[j]; }
    }
    *(float4*)&red[w][lane*8]       = make_float4(pA[0],pA[1],pA[2],pA[3]);
    *(float4*)&red[w][lane*8+4]     = make_float4(pA[4],pA[5],pA[6],pA[7]);
    *(float4*)&red[w][256+lane*8]   = make_float4(pB[0],pB[1],pB[2],pB[3]);
    *(float4*)&red[w][256+lane*8+4] = make_float4(pB[4],pB[5],pB[6],pB[7]);
    __syncthreads();

    float4 r0 = *(float4*)&red[0][tid*4];
    float4 r1 = *(float4*)&red[1][tid*4];
    float4 r2 = *(float4*)&red[2][tid*4];
    float4 r3 = *(float4*)&red[3][tid*4];
    float4 o;
    o.x = r0.x + r1.x + r2.x + r3.x;
    o.y = r0.y + r1.y + r2.y + r3.y;
    o.z = r0.z + r1.z + r2.z + r3.z;
    o.w = r0.w + r1.w + r2.w + r3.w;
    *(float4*)(g_PO + b * 512 + tid * 4) = o;
}

// =================================================================================
// k_ctxout: fused  CTX = PO_h @ Wv_h  (64x128 tile, K=256 per head)
//           then   Y = CTX @ Wo + gate/agg/LayerNorm epilogue
// smem (floats): AsRM [2][2][64][20] @0 | Bs [2][16][128] @5120
//                Bs2 [2][16][256] @0 (stage2, overlaps) | Cs [64][132] @9216
// total 17664 floats = 70656 B dynamic
// =================================================================================
#define CO_SMEM_BYTES (17664 * 4)

__global__ void __launch_bounds__(256, 2) k_ctxout(const float* __restrict__ Wv,
                                                   const float* __restrict__ Wo,
                                                   const float* __restrict__ Cc,
                                                   const float* __restrict__ Wg,
                                                   const float* __restrict__ bgp,
                                                   const float* __restrict__ gamma,
                                                   const float* __restrict__ beta,
                                                   float* __restrict__ O) {
    extern __shared__ float sm[];
    float* AsRM = sm;            // [buf][head][r(64)][kpad20]
    float* Bs   = sm + 5120;     // [buf][kk(16)][128]
    float* Bs2  = sm;            // stage2: [buf][kk(16)][256]
    float* Cs   = sm + 9216;     // [r(64)][132]
    int tid = threadIdx.x;
    long row0 = (long)blockIdx.x * 64;

    // ---------------- stage 1: ctx tile 64x128 ----------------
    {
        int tx = tid & 15, ty = tid >> 4;
        int hh = tx >> 3;
        ull acc1[4][4];
        #pragma unroll
        for (int i = 0; i < 4; i++)
            #pragma unroll
            for (int j = 0; j < 4; j++) acc1[i][j] = 0ULL;

        auto issueS1 = [&](int ch, int b2) {
            int k0 = ch * 16;
            #pragma unroll
            for (int it = 0; it < 2; it++) {
                int t = tid + it * 256;
                int hd = t >> 8, r = (t >> 2) & 63, f = t & 3;
                cpa(s2u(&AsRM[b2*2560 + hd*1280 + r*20 + f*4]),
                    g_PO + (row0 + r)*512 + hd*256 + k0 + f*4);
            }
            #pragma unroll
            for (int it = 0; it < 2; it++) {
                int t = tid + it * 256;
                int kk = t >> 5, c = (t & 31) * 4;
                cpa(s2u(&Bs[b2*2048 + kk*128 + c]), Wv + (long)(k0 + kk)*128 + c);
            }
            cpc();
        };

        issueS1(0, 0);
        int buf = 0;
        for (int ch = 0; ch < 16; ch++) {
            if (ch + 1 < 16) { issueS1(ch + 1, buf ^ 1); cpw<1>(); } else { cpw<0>(); }
            __syncthreads();
            const float* bb = &Bs[buf*2048];
            const float* aa = &AsRM[buf*2560 + hh*1280];
            #pragma unroll
            for (int kk = 0; kk < 16; kk++) {
                float4 b0 = *(const float4*)&bb[kk*128 + tx*8];
                float4 b1 = *(const float4*)&bb[kk*128 + tx*8 + 4];
                ull bp0 = pk2(b0.x,b0.y), bp1 = pk2(b0.z,b0.w);
                ull bp2 = pk2(b1.x,b1.y), bp3 = pk2(b1.z,b1.w);
                #pragma unroll
                for (int i = 0; i < 4; i++) {
                    float a = aa[(ty*4+i)*20 + kk];
                    ull a2 = pk2(a, a);
                    fma2(acc1[i][0], a2, bp0); fma2(acc1[i][1], a2, bp1);
                    fma2(acc1[i][2], a2, bp2); fma2(acc1[i][3], a2, bp3);
                }
            }
            __syncthreads();
            buf ^= 1;
        }

        // stage ctx into smem (row-major, pad 132)
        #pragma unroll
        for (int i = 0; i < 4; i++) {
            float2 f0 = up2(acc1[i][0]), f1 = up2(acc1[i][1]);
            float2 f2 = up2(acc1[i][2]), f3 = up2(acc1[i][3]);
            int r = ty*4 + i;
            *(float4*)&Cs[r*132 + tx*8]     = make_float4(f0.x, f0.y, f1.x, f1.y);
            *(float4*)&Cs[r*132 + tx*8 + 4] = make_float4(f2.x, f2.y, f3.x, f3.y);
        }
        __syncthreads();
    }

    // ---------------- stage 2: Y = ctx @ Wo + epilogue ----------------
    int lane = tid & 31, w = tid >> 5;
    ull acc[8][4];
    #pragma unroll
    for (int i = 0; i < 8; i++)
        #pragma unroll
        for (int j = 0; j < 4; j++) acc[i][j] = 0ULL;

    auto issueS2 = [&](int ch, int b2) {
        int k0 = ch * 16;
        #pragma unroll
        for (int it = 0; it < 4; it++) {
            int t = tid + it * 256;
            int kk = t >> 6, c = (t & 63) * 4;
            cpa(s2u(&Bs2[b2*4096 + kk*256 + c]), Wo + (long)(k0 + kk)*256 + c);
        }
        cpc();
    };

    issueS2(0, 0);
    int buf = 0;
    for (int ch = 0; ch < 8; ch++) {
        if (ch + 1 < 8) { issueS2(ch + 1, buf ^ 1); cpw<1>(); } else { cpw<0>(); }
        __syncthreads();
        const float* bb = &Bs2[buf*4096];
        int k0 = ch * 16;
        #pragma unroll
        for (int kk = 0; kk < 16; kk++) {
            float4 b0 = *(const float4*)&bb[kk*256 + lane*8];
            float4 b1 = *(const float4*)&bb[kk*256 + lane*8 + 4];
            ull bp0 = pk2(b0.x,b0.y), bp1 = pk2(b0.z,b0.w);
            ull bp2 = pk2(b1.x,b1.y), bp3 = pk2(b1.z,b1.w);
            #pragma unroll
            for (int i = 0; i < 8; i++) {
                float a = Cs[(w*8+i)*132 + k0 + kk];
                ull a2 = pk2(a, a);
                fma2(acc[i][0], a2, bp0); fma2(acc[i][1], a2, bp1);
                fma2(acc[i][2], a2, bp2); fma2(acc[i][3], a2, bp3);
            }
        }
        __syncthreads();
        buf ^= 1;
    }

    // ---- epilogue: gate + agg + LayerNorm ----
    float4 wg0 = *(const float4*)(Wg + lane*8);
    float4 wg1 = *(const float4*)(Wg + lane*8 + 4);
    float4 wh0 = *(const float4*)(Wg + 256 + lane*8);
    float4 wh1 = *(const float4*)(Wg + 256 + lane*8 + 4);
    float4 gm0 = *(const float4*)(gamma + lane*8);
    float4 gm1 = *(const float4*)(gamma + lane*8 + 4);
    float4 bt0 = *(const float4*)(beta + lane*8);
    float4 bt1 = *(const float4*)(beta + lane*8 + 4);
    float bgv = bgp[0];

    #pragma unroll
    for (int i = 0; i < 8; i++) {
        long gb = row0 + w*8 + i;
        const float* cr = Cc + gb * 256 + lane * 8;
        float4 c0 = *(const float4*)(cr);
        float4 c1 = *(const float4*)(cr + 4);
        float2 u0 = up2(acc[i][0]), u1 = up2(acc[i][1]);
        float2 u2 = up2(acc[i][2]), u3 = up2(acc[i][3]);
        float x[8] = {u0.x,u0.y,u1.x,u1.y,u2.x,u2.y,u3.x,u3.y};
        float cc[8] = {c0.x,c0.y,c0.z,c0.w,c1.x,c1.y,c1.z,c1.w};
        float wgv[8] = {wg0.x,wg0.y,wg0.z,wg0.w,wg1.x,wg1.y,wg1.z,wg1.w};
        float whv[8] = {wh0.x,wh0.y,wh0.z,wh0.w,wh1.x,wh1.y,wh1.z,wh1.w};
        float s = 0.f;
        #pragma unroll
        for (int j = 0; j < 8; j++) s += cc[j]*wgv[j] + x[j]*whv[j];
        s = wredsum(s) + bgv;
        float gate = 1.f / (1.f + expf(-s));
        float a[8], su = 0.f, sq = 0.f;
        #pragma unroll
        for (int j = 0; j < 8; j++) {
            a[j] = gate * cc[j] + (1.f - gate) * x[j];
            su += a[j]; sq += a[j]*a[j];
        }
        su = wredsum(su); sq = wredsum(sq);
        float mu  = su * (1.f/256.f);
        float inv = rsqrtf(sq * (1.f/256.f) - mu*mu + 1e-5f);
        float gv[8] = {gm0.x,gm0.y,gm0.z,gm0.w,gm1.x,gm1.y,gm1.z,gm1.w};
        float bv[8] = {bt0.x,bt0.y,bt0.z,bt0.w,bt1.x,bt1.y,bt1.z,bt1.w};
        float o[8];
        #pragma unroll
        for (int j = 0; j < 8; j++) o[j] = (a[j]-mu)*inv*gv[j] + bv[j];
        *(float4*)(O + gb*256 + lane*8)     = make_float4(o[0],o[1],o[2],o[3]);
        *(float4*)(O + gb*256 + lane*8 + 4) = make_float4(o[4],o[5],o[6],o[7]);
    }
}

// =================================================================================
extern "C" void kernel_launch(void* const* d_in, const int* in_sizes, int n_in,
                              void* d_out, int out_size) {
    const float* C     = (const float*)d_in[0];
    const float* AE    = (const float*)d_in[1];
    const int*   NI    = (const int*)  d_in[2];
    const float* NW    = (const float*)d_in[3];
    const float* Wq    = (const float*)d_in[4];
    const float* Wk    = (const float*)d_in[5];
    const float* Wv    = (const float*)d_in[6];
    const float* Wo    = (const float*)d_in[7];
    const float* Wg    = (const float*)d_in[8];
    const float* bg    = (const float*)d_in[9];
    const float* gamma = (const float*)d_in[10];
    const float* beta  = (const float*)d_in[11];
    float* out = (float*)d_out;

    int B = in_sizes[0] / EMBED_DIM;
    if (B > MAXB) B = MAXB;

    cudaFuncSetAttribute(k_qrk,    cudaFuncAttributeMaxDynamicSharedMemorySize, QRK_SMEM_BYTES);
    cudaFuncSetAttribute(k_ctxout, cudaFuncAttributeMaxDynamicSharedMemorySize, CO_SMEM_BYTES);

    k_tr    <<< 128, 256 >>>(Wk);
    k_qrk   <<< B / 128, 256, QRK_SMEM_BYTES >>>(C, Wq);
    k_gather<<< B, 128 >>>(AE, NI, NW);
    k_ctxout<<< B / 64, 256, CO_SMEM_BYTES >>>(Wv, Wo, C, Wg, bg, gamma, beta, out);
}

// round 4
// speedup vs baseline: 1.0678x; 1.0006x over previous
#include <cuda_runtime.h>
#include <cuda_bf16.h>
#include <math.h>

#define EMBED_DIM 256
#define MAXB 32768

typedef unsigned long long ull;

// ---------------- scratch (device globals; no allocation allowed) ----------------
__device__ float g_RK [(size_t)MAXB * 512];   // rk = Wk_h q_h      [B,2,256]
__device__ float g_PO [(size_t)MAXB * 512];   // attn-pooled nb     [B,2,256]
__device__ float g_WkT[128 * 256];            // Wk transposed [j][d]

// ---------------- f32x2 helpers ----------------
__device__ __forceinline__ ull pk2(float x, float y) {
    ull r; asm("mov.b64 %0, {%1, %2};" : "=l"(r) : "f"(x), "f"(y)); return r;
}
__device__ __forceinline__ void fma2(ull &d, ull a, ull b) {
    asm("fma.rn.f32x2 %0, %1, %2, %0;" : "+l"(d) : "l"(a), "l"(b));
}
__device__ __forceinline__ float2 up2(ull v) {
    float2 r; asm("mov.b64 {%0, %1}, %2;" : "=f"(r.x), "=f"(r.y) : "l"(v)); return r;
}
__device__ __forceinline__ float wredsum(float v) {
    #pragma unroll
    for (int o = 16; o >= 1; o >>= 1) v += __shfl_xor_sync(0xffffffffu, v, o);
    return v;
}

// ---------------- cp.async helpers ----------------
__device__ __forceinline__ unsigned s2u(const void* p) {
    return (unsigned)__cvta_generic_to_shared(p);
}
__device__ __forceinline__ void cpa(unsigned s, const void* g) {
    asm volatile("cp.async.cg.shared.global [%0], [%1], 16;" :: "r"(s), "l"(g) : "memory");
}
__device__ __forceinline__ void cpc() {
    asm volatile("cp.async.commit_group;" ::: "memory");
}
template<int N> __device__ __forceinline__ void cpw() {
    asm volatile("cp.async.wait_group %0;" :: "n"(N) : "memory");
}

// =================================================================================
// k_tr: g_WkT[j][d] = Wk[d][j]    (128x256 <- 256x128)
// =================================================================================
__global__ void __launch_bounds__(256) k_tr(const float* __restrict__ Wk) {
    int idx = blockIdx.x * 256 + threadIdx.x;   // 0..32767
    int j = idx >> 8, d = idx & 255;
    g_WkT[j * 256 + d] = Wk[d * 128 + j];
}

// =================================================================================
// k_qrk: fused  Q = C@Wq  (tile 128x128, K=256)  then  RK = Q_h @ Wk_h^T
// smem (floats): AsRM [2][128][20] @0 | Bs [2][16][128] @5120 | Qs [128][132] @9216
// total 26112 floats = 104448 B dynamic
// =================================================================================
#define QRK_SMEM_BYTES (26112 * 4)

__global__ void __launch_bounds__(256, 2) k_qrk(const float* __restrict__ C,
                                                const float* __restrict__ Wq) {
    extern __shared__ float sm[];
    float* AsRM = sm;            // [buf][r(128)][kpad20]
    float* Bs   = sm + 5120;     // [buf][kk(16)][128]
    float* Qs   = sm + 9216;     // [r(128)][132]
    int tid = threadIdx.x;
    int tx = tid & 15, ty = tid >> 4;
    long row0 = (long)blockIdx.x * 128;

    ull acc[8][4];
    #pragma unroll
    for (int i = 0; i < 8; i++)
        #pragma unroll
        for (int j = 0; j < 4; j++) acc[i][j] = 0ULL;

    // ---------------- stage 1: Q tile ----------------
    auto issue1 = [&](int ch, int buf) {
        int k0 = ch * 16;
        #pragma unroll
        for (int it = 0; it < 2; it++) {
            int t = tid + it * 256;
            int r = t >> 2, f = t & 3;
            cpa(s2u(&AsRM[buf*2560 + r*20 + f*4]), C + (row0 + r)*256 + k0 + f*4);
        }
        #pragma unroll
        for (int it = 0; it < 2; it++) {
            int t = tid + it * 256;
            int kk = t >> 5, c = (t & 31) * 4;
            cpa(s2u(&Bs[buf*2048 + kk*128 + c]), Wq + (long)(k0 + kk)*128 + c);
        }
        cpc();
    };

    issue1(0, 0);
    int buf = 0;
    for (int ch = 0; ch < 16; ch++) {
        if (ch + 1 < 16) { issue1(ch + 1, buf ^ 1); cpw<1>(); } else { cpw<0>(); }
        __syncthreads();
        const float* bb = &Bs[buf*2048];
        const float* aa = &AsRM[buf*2560];
        #pragma unroll
        for (int kk = 0; kk < 16; kk++) {
            float4 b0 = *(const float4*)&bb[kk*128 + tx*8];
            float4 b1 = *(const float4*)&bb[kk*128 + tx*8 + 4];
            ull bp0 = pk2(b0.x,b0.y), bp1 = pk2(b0.z,b0.w);
            ull bp2 = pk2(b1.x,b1.y), bp3 = pk2(b1.z,b1.w);
            #pragma unroll
            for (int i = 0; i < 8; i++) {
                float a = aa[(ty*8+i)*20 + kk];
                ull a2 = pk2(a, a);
                fma2(acc[i][0], a2, bp0); fma2(acc[i][1], a2, bp1);
                fma2(acc[i][2], a2, bp2); fma2(acc[i][3], a2, bp3);
            }
        }
        __syncthreads();
        buf ^= 1;
    }

    // stage-1 epilogue: stage Q tile into smem (row-major, pad 132)
    #pragma unroll
    for (int i = 0; i < 8; i++) {
        float2 f0 = up2(acc[i][0]), f1 = up2(acc[i][1]);
        float2 f2 = up2(acc[i][2]), f3 = up2(acc[i][3]);
        int r = ty*8 + i;
        *(float4*)&Qs[r*132 + tx*8]     = make_float4(f0.x, f0.y, f1.x, f1.y);
        *(float4*)&Qs[r*132 + tx*8 + 4] = make_float4(f2.x, f2.y, f3.x, f3.y);
    }
    __syncthreads();

    // ---------------- stage 2: RK = Q_h @ Wk_h^T  (4 col-chunks of 128, K=64) ----------------
    auto issue2 = [&](int g, int b2) {
        int cc = g >> 2, kc = g & 3;
        int h = cc >> 1, d0 = (cc & 1) * 128;
        int j0 = h*64 + kc*16;
        #pragma unroll
        for (int it = 0; it < 2; it++) {
            int t = tid + it * 256;
            int kk = t >> 5, c = (t & 31) * 4;
            cpa(s2u(&Bs[b2*2048 + kk*128 + c]), g_WkT + (j0 + kk)*256 + d0 + c);
        }
        cpc();
    };

    issue2(0, 0);
    buf = 0;
    for (int g = 0; g < 16; g++) {
        int cc = g >> 2, kc = g & 3;
        int h = cc >> 1;
        if ((g & 3) == 0) {
            #pragma unroll
            for (int i = 0; i < 8; i++)
                #pragma unroll
                for (int j = 0; j < 4; j++) acc[i][j] = 0ULL;
        }
        if (g + 1 < 16) { issue2(g + 1, buf ^ 1); cpw<1>(); } else { cpw<0>(); }
        __syncthreads();
        const float* bb = &Bs[buf*2048];
        int j0 = h*64 + kc*16;
        #pragma unroll
        for (int kk = 0; kk < 16; kk++) {
            float4 b0 = *(const float4*)&bb[kk*128 + tx*8];
            float4 b1 = *(const float4*)&bb[kk*128 + tx*8 + 4];
            ull bp0 = pk2(b0.x,b0.y), bp1 = pk2(b0.z,b0.w);
            ull bp2 = pk2(b1.x,b1.y), bp3 = pk2(b1.z,b1.w);
            #pragma unroll
            for (int i = 0; i < 8; i++) {
                float a = Qs[(ty*8+i)*132 + j0 + kk];
                ull a2 = pk2(a, a);
                fma2(acc[i][0], a2, bp0); fma2(acc[i][1], a2, bp1);
                fma2(acc[i][2], a2, bp2); fma2(acc[i][3], a2, bp3);
            }
        }
        __syncthreads();
        if ((g & 3) == 3) {
            #pragma unroll
            for (int i = 0; i < 8; i++) {
                float2 f0 = up2(acc[i][0]), f1 = up2(acc[i][1]);
                float2 f2 = up2(acc[i][2]), f3 = up2(acc[i][3]);
                long r = row0 + ty*8 + i;
                *(float4*)(g_RK + r*512 + cc*128 + tx*8)     = make_float4(f0.x, f0.y, f1.x, f1.y);
                *(float4*)(g_RK + r*512 + cc*128 + tx*8 + 4) = make_float4(f2.x, f2.y, f3.x, f3.y);
            }
        }
        buf ^= 1;
    }
}

// =================================================================================
// k_gather: gather + scores + softmax + pooled. One CTA (128 thr) per batch row.
// =================================================================================
__global__ void __launch_bounds__(128) k_gather(const float* __restrict__ AE,
                                                const int*   __restrict__ NI,
                                                const float* __restrict__ NW) {
    __shared__ float sc_s[2][16];
    __shared__ float attn_s[2][16];
    __shared__ __align__(16) float red[4][512];

    long b   = blockIdx.x;
    int tid  = threadIdx.x;
    int lane = tid & 31, w = tid >> 5;

    const float* rkb = g_RK + b * 512;
    float4 rA0 = *(const float4*)(rkb + lane*8);
    float4 rA1 = *(const float4*)(rkb + lane*8 + 4);
    float4 rB0 = *(const float4*)(rkb + 256 + lane*8);
    float4 rB1 = *(const float4*)(rkb + 256 + lane*8 + 4);

    int idx[4];
    #pragma unroll
    for (int q = 0; q < 4; q++) idx[q] = __ldg(NI + b * 16 + w * 4 + q);

    float4 v0[4], v1[4];
    #pragma unroll
    for (int q = 0; q < 4; q++) {
        const float* base = AE + (size_t)idx[q] * 256 + lane * 8;
        v0[q] = *(const float4*)(base);
        v1[q] = *(const float4*)(base + 4);
    }

    #pragma unroll
    for (int q = 0; q < 4; q++) {
        int k = w*4 + q;
        float s0 = v0[q].x*rA0.x + v0[q].y*rA0.y + v0[q].z*rA0.z + v0[q].w*rA0.w
                 + v1[q].x*rA1.x + v1[q].y*rA1.y + v1[q].z*rA1.z + v1[q].w*rA1.w;
        float s1 = v0[q].x*rB0.x + v0[q].y*rB0.y + v0[q].z*rB0.z + v0[q].w*rB0.w
                 + v1[q].x*rB1.x + v1[q].y*rB1.y + v1[q].z*rB1.z + v1[q].w*rB1.w;
        s0 = wredsum(s0);
        s1 = wredsum(s1);
        if (lane == 0) { sc_s[0][k] = s0; sc_s[1][k] = s1; }
    }
    __syncthreads();

    if (tid < 32) {
        int h = tid >> 4, k = tid & 15;
        float lw = NW[b * 16 + k];
        float s = sc_s[h][k] * 0.125f + logf(fmaxf(lw, 1e-6f) + 1e-6f);
        float m = s;
        #pragma unroll
        for (int o = 8; o >= 1; o >>= 1) m = fmaxf(m, __shfl_xor_sync(0xffffffffu, m, o));
        float e = expf(s - m);
        float sum = e;
        #pragma unroll
        for (int o = 8; o >= 1; o >>= 1) sum += __shfl_xor_sync(0xffffffffu, sum, o);
        attn_s[h][k] = e / sum;
    }
    __syncthreads();

    float pA[8] = {0,0,0,0,0,0,0,0};
    float pB[8] = {0,0,0,0,0,0,0,0};
    #pragma unroll
    for (int q = 0; q < 4; q++) {
        float a0 = attn_s[0][w*4+q], a1 = attn_s[1][w*4+q];
        float vv[8] = {v0[q].x,v0[q].y,v0[q].z,v0[q].w,v1[q].x,v1[q].y,v1[q].z,v1[q].w};
        #pragma unroll
        for (int j = 0; j < 8; j++) { pA[j] += a0 * vv[j]; pB[j] += a1 * vv[j]; }
    }
    *(float4*)&red[w][lane*8]       = make_float4(pA[0],pA[1],pA[2],pA[3]);
    *(float4*)&red[w][lane*8+4]     = make_float4(pA[4],pA[5],pA[6],pA[7]);
    *(float4*)&red[w][256+lane*8]   = make_float4(pB[0],pB[1],pB[2],pB[3]);
    *(float4*)&red[w][256+lane*8+4] = make_float4(pB[4],pB[5],pB[6],pB[7]);
    __syncthreads();

    float4 r0 = *(float4*)&red[0][tid*4];
    float4 r1 = *(float4*)&red[1][tid*4];
    float4 r2 = *(float4*)&red[2][tid*4];
    float4 r3 = *(float4*)&red[3][tid*4];
    float4 o;
    o.x = r0.x + r1.x + r2.x + r3.x;
    o.y = r0.y + r1.y + r2.y + r3.y;
    o.z = r0.z + r1.z + r2.z + r3.z;
    o.w = r0.w + r1.w + r2.w + r3.w;
    *(float4*)(g_PO + b * 512 + tid * 4) = o;
}

// =================================================================================
// k_ctxout: fused  CTX = PO_h @ Wv_h  (64x128 tile, K=256 per head)
//           then   Y = CTX @ Wo + gate/agg/LayerNorm epilogue
// smem (floats): AsRM [2][2][64][20] @0 | Bs [2][16][128] @5120
//                Bs2 [2][16][256] @0 (stage2, overlaps) | Cs [64][132] @9216
// total 17664 floats = 70656 B dynamic
// =================================================================================
#define CO_SMEM_BYTES (17664 * 4)

__global__ void __launch_bounds__(256, 2) k_ctxout(const float* __restrict__ Wv,
                                                   const float* __restrict__ Wo,
                                                   const float* __restrict__ Cc,
                                                   const float* __restrict__ Wg,
                                                   const float* __restrict__ bgp,
                                                   const float* __restrict__ gamma,
                                                   const float* __restrict__ beta,
                                                   float* __restrict__ O) {
    extern __shared__ float sm[];
    float* AsRM = sm;            // [buf][head][r(64)][kpad20]
    float* Bs   = sm + 5120;     // [buf][kk(16)][128]
    float* Bs2  = sm;            // stage2: [buf][kk(16)][256]
    float* Cs   = sm + 9216;     // [r(64)][132]
    int tid = threadIdx.x;
    long row0 = (long)blockIdx.x * 64;

    // ---------------- stage 1: ctx tile 64x128 ----------------
    {
        int tx = tid & 15, ty = tid >> 4;
        int hh = tx >> 3;
        ull acc1[4][4];
        #pragma unroll
        for (int i = 0; i < 4; i++)
            #pragma unroll
            for (int j = 0; j < 4; j++) acc1[i][j] = 0ULL;

        auto issueS1 = [&](int ch, int b2) {
            int k0 = ch * 16;
            #pragma unroll
            for (int it = 0; it < 2; it++) {
                int t = tid + it * 256;
                int hd = t >> 8, r = (t >> 2) & 63, f = t & 3;
                cpa(s2u(&AsRM[b2*2560 + hd*1280 + r*20 + f*4]),
                    g_PO + (row0 + r)*512 + hd*256 + k0 + f*4);
            }
            #pragma unroll
            for (int it = 0; it < 2; it++) {
                int t = tid + it * 256;
                int kk = t >> 5, c = (t & 31) * 4;
                cpa(s2u(&Bs[b2*2048 + kk*128 + c]), Wv + (long)(k0 + kk)*128 + c);
            }
            cpc();
        };

        issueS1(0, 0);
        int buf = 0;
        for (int ch = 0; ch < 16; ch++) {
            if (ch + 1 < 16) { issueS1(ch + 1, buf ^ 1); cpw<1>(); } else { cpw<0>(); }
            __syncthreads();
            const float* bb = &Bs[buf*2048];
            const float* aa = &AsRM[buf*2560 + hh*1280];
            #pragma unroll
            for (int kk = 0; kk < 16; kk++) {
                float4 b0 = *(const float4*)&bb[kk*128 + tx*8];
                float4 b1 = *(const float4*)&bb[kk*128 + tx*8 + 4];
                ull bp0 = pk2(b0.x,b0.y), bp1 = pk2(b0.z,b0.w);
                ull bp2 = pk2(b1.x,b1.y), bp3 = pk2(b1.z,b1.w);
                #pragma unroll
                for (int i = 0; i < 4; i++) {
                    float a = aa[(ty*4+i)*20 + kk];
                    ull a2 = pk2(a, a);
                    fma2(acc1[i][0], a2, bp0); fma2(acc1[i][1], a2, bp1);
                    fma2(acc1[i][2], a2, bp2); fma2(acc1[i][3], a2, bp3);
                }
            }
            __syncthreads();
            buf ^= 1;
        }

        // stage ctx into smem (row-major, pad 132)
        #pragma unroll
        for (int i = 0; i < 4; i++) {
            float2 f0 = up2(acc1[i][0]), f1 = up2(acc1[i][1]);
            float2 f2 = up2(acc1[i][2]), f3 = up2(acc1[i][3]);
            int r = ty*4 + i;
            *(float4*)&Cs[r*132 + tx*8]     = make_float4(f0.x, f0.y, f1.x, f1.y);
            *(float4*)&Cs[r*132 + tx*8 + 4] = make_float4(f2.x, f2.y, f3.x, f3.y);
        }
        __syncthreads();
    }

    // ---------------- stage 2: Y = ctx @ Wo + epilogue ----------------
    int lane = tid & 31, w = tid >> 5;
    ull acc[8][4];
    #pragma unroll
    for (int i = 0; i < 8; i++)
        #pragma unroll
        for (int j = 0; j < 4; j++) acc[i][j] = 0ULL;

    auto issueS2 = [&](int ch, int b2) {
        int k0 = ch * 16;
        #pragma unroll
        for (int it = 0; it < 4; it++) {
            int t = tid + it * 256;
            int kk = t >> 6, c = (t & 63) * 4;
            cpa(s2u(&Bs2[b2*4096 + kk*256 + c]), Wo + (long)(k0 + kk)*256 + c);
        }
        cpc();
    };

    issueS2(0, 0);
    int buf = 0;
    for (int ch = 0; ch < 8; ch++) {
        if (ch + 1 < 8) { issueS2(ch + 1, buf ^ 1); cpw<1>(); } else { cpw<0>(); }
        __syncthreads();
        const float* bb = &Bs2[buf*4096];
        int k0 = ch * 16;
        #pragma unroll
        for (int kk = 0; kk < 16; kk++) {
            float4 b0 = *(const float4*)&bb[kk*256 + lane*8];
            float4 b1 = *(const float4*)&bb[kk*256 + lane*8 + 4];
            ull bp0 = pk2(b0.x,b0.y), bp1 = pk2(b0.z,b0.w);
            ull bp2 = pk2(b1.x,b1.y), bp3 = pk2(b1.z,b1.w);
            #pragma unroll
            for (int i = 0; i < 8; i++) {
                float a = Cs[(w*8+i)*132 + k0 + kk];
                ull a2 = pk2(a, a);
                fma2(acc[i][0], a2, bp0); fma2(acc[i][1], a2, bp1);
                fma2(acc[i][2], a2, bp2); fma2(acc[i][3], a2, bp3);
            }
        }
        __syncthreads();
        buf ^= 1;
    }

    // ---- epilogue: gate + agg + LayerNorm ----
    float4 wg0 = *(const float4*)(Wg + lane*8);
    float4 wg1 = *(const float4*)(Wg + lane*8 + 4);
    float4 wh0 = *(const float4*)(Wg + 256 + lane*8);
    float4 wh1 = *(const float4*)(Wg + 256 + lane*8 + 4);
    float4 gm0 = *(const float4*)(gamma + lane*8);
    float4 gm1 = *(const float4*)(gamma + lane*8 + 4);
    float4 bt0 = *(const float4*)(beta + lane*8);
    float4 bt1 = *(const float4*)(beta + lane*8 + 4);
    float bgv = bgp[0];

    #pragma unroll
    for (int i = 0; i < 8; i++) {
        long gb = row0 + w*8 + i;
        const float* cr = Cc + gb * 256 + lane * 8;
        float4 c0 = *(const float4*)(cr);
        float4 c1 = *(const float4*)(cr + 4);
        float2 u0 = up2(acc[i][0]), u1 = up2(acc[i][1]);
        float2 u2 = up2(acc[i][2]), u3 = up2(acc[i][3]);
        float x[8] = {u0.x,u0.y,u1.x,u1.y,u2.x,u2.y,u3.x,u3.y};
        float cc[8] = {c0.x,c0.y,c0.z,c0.w,c1.x,c1.y,c1.z,c1.w};
        float wgv[8] = {wg0.x,wg0.y,wg0.z,wg0.w,wg1.x,wg1.y,wg1.z,wg1.w};
        float whv[8] = {wh0.x,wh0.y,wh0.z,wh0.w,wh1.x,wh1.y,wh1.z,wh1.w};
        float s = 0.f;
        #pragma unroll
        for (int j = 0; j < 8; j++) s += cc[j]*wgv[j] + x[j]*whv[j];
        s = wredsum(s) + bgv;
        float gate = 1.f / (1.f + expf(-s));
        float a[8], su = 0.f, sq = 0.f;
        #pragma unroll
        for (int j = 0; j < 8; j++) {
            a[j] = gate * cc[j] + (1.f - gate) * x[j];
            su += a[j]; sq += a[j]*a[j];
        }
        su = wredsum(su); sq = wredsum(sq);
        float mu  = su * (1.f/256.f);
        float inv = rsqrtf(sq * (1.f/256.f) - mu*mu + 1e-5f);
        float gv[8] = {gm0.x,gm0.y,gm0.z,gm0.w,gm1.x,gm1.y,gm1.z,gm1.w};
        float bv[8] = {bt0.x,bt0.y,bt0.z,bt0.w,bt1.x,bt1.y,bt1.z,bt1.w};
        float o[8];
        #pragma unroll
        for (int j = 0; j < 8; j++) o[j] = (a[j]-mu)*inv*gv[j] + bv[j];
        *(float4*)(O + gb*256 + lane*8)     = make_float4(o[0],o[1],o[2],o[3]);
        *(float4*)(O + gb*256 + lane*8 + 4) = make_float4(o[4],o[5],o[6],o[7]);
    }
}

// =================================================================================
extern "C" void kernel_launch(void* const* d_in, const int* in_sizes, int n_in,
                              void* d_out, int out_size) {
    const float* C     = (const float*)d_in[0];
    const float* AE    = (const float*)d_in[1];
    const int*   NI    = (const int*)  d_in[2];
    const float* NW    = (const float*)d_in[3];
    const float* Wq    = (const float*)d_in[4];
    const float* Wk    = (const float*)d_in[5];
    const float* Wv    = (const float*)d_in[6];
    const float* Wo    = (const float*)d_in[7];
    const float* Wg    = (const float*)d_in[8];
    const float* bg    = (const float*)d_in[9];
    const float* gamma = (const float*)d_in[10];
    const float* beta  = (const float*)d_in[11];
    float* out = (float*)d_out;

    int B = in_sizes[0] / EMBED_DIM;
    if (B > MAXB) B = MAXB;

    cudaFuncSetAttribute(k_qrk,    cudaFuncAttributeMaxDynamicSharedMemorySize, QRK_SMEM_BYTES);
    cudaFuncSetAttribute(k_ctxout, cudaFuncAttributeMaxDynamicSharedMemorySize, CO_SMEM_BYTES);

    k_tr    <<< 128, 256 >>>(Wk);
    k_qrk   <<< B / 128, 256, QRK_SMEM_BYTES >>>(C, Wq);
    k_gather<<< B, 128 >>>(AE, NI, NW);
    k_ctxout<<< B / 64, 256, CO_SMEM_BYTES >>>(Wv, Wo, C, Wg, bg, gamma, beta, out);
}